// round 2
// baseline (speedup 1.0000x reference)
#include <cuda_runtime.h>

#define HH 512
#define WW 512
#define HWSZ (HH * WW)
#define TILE_ROWS 32
#define SROWS (TILE_ROWS + 4)      // 36 rows incl. 2-row halo each side
#define WPR 18                      // 16 data words + 1 zero pad word each side
#define MAXBLK 2048

// per-block partials: [quantity][block]  q: 0=focal 1=sum(p*t) 2=sum(p) 3=sum(t) 4=sum(bce*w)
__device__ float g_part[5 * MAXBLK];

__global__ void __launch_bounds__(256) combined_loss_kernel(
    const float* __restrict__ inp,
    const float* __restrict__ tgt)
{
    __shared__ unsigned sbits[SROWS * WPR];   // 648 words = 2.6 KB

    const int tilesPerImg = HH / TILE_ROWS;   // 16
    const int img  = blockIdx.x / tilesPerImg;
    const int tile = blockIdx.x - img * tilesPerImg;
    const int y0   = tile * TILE_ROWS;

    const float* tb = tgt + (size_t)img * HWSZ;
    const float* ib = inp + (size_t)img * HWSZ;

    const int wid  = threadIdx.x >> 5;
    const int lane = threadIdx.x & 31;

    // ---- phase 1: pack target bits into smem (1 bit per pixel) ----
    // zero the pad words
    for (int r = threadIdx.x; r < SROWS; r += 256) {
        sbits[r * WPR] = 0u;
        sbits[r * WPR + 17] = 0u;
    }
    // 576 word-tasks: r = task>>4 (smem row), w16 = task&15 (word within row)
    for (int task = wid; task < SROWS * 16; task += 8) {
        const int r   = task >> 4;
        const int w16 = task & 15;
        const int gy  = y0 - 2 + r;
        unsigned bits = 0u;
        if (gy >= 0 && gy < HH) {                 // uniform per warp
            float v = tb[gy * WW + (w16 << 5) + lane];
            bits = __ballot_sync(0xFFFFFFFFu, v > 0.5f);
        }
        if (lane == 0) sbits[r * WPR + 1 + w16] = bits;
    }
    __syncthreads();

    // ---- phase 2: per-pixel math + boundary from smem bits ----
    float a_focal = 0.f, a_spt = 0.f, a_sp = 0.f, a_st = 0.f, a_sbw = 0.f;

    #pragma unroll 4
    for (int i = 0; i < 16; i++) {
        const int g  = threadIdx.x + (i << 8);   // 0..4095 groups in tile
        const int ry = g >> 7;                   // tile row 0..31
        const int x0 = (g & 127) << 2;           // col of first pixel
        const int gy = y0 + ry;

        const float4 xi = *reinterpret_cast<const float4*>(ib + gy * WW + x0);

        // 8-bit windows starting at column x0-2 (padded bit index x0+30)
        const int sb = x0 + 30;
        const int w  = sb >> 5;
        const int s  = sb & 31;
        const int bC = (ry + 2) * WPR + w;       // smem row for gy is ry+2
        const unsigned winC  = __funnelshift_r(sbits[bC],           sbits[bC + 1],           s);
        const unsigned winU1 = __funnelshift_r(sbits[bC - WPR],     sbits[bC - WPR + 1],     s);
        const unsigned winD1 = __funnelshift_r(sbits[bC + WPR],     sbits[bC + WPR + 1],     s);
        const unsigned winU2 = __funnelshift_r(sbits[bC - 2*WPR],   sbits[bC - 2*WPR + 1],   s);
        const unsigned winD2 = __funnelshift_r(sbits[bC + 2*WPR],   sbits[bC + 2*WPR + 1],   s);

        const float xv[4] = { xi.x, xi.y, xi.z, xi.w };

        #pragma unroll
        for (int j = 0; j < 4; j++) {
            const float x = xv[j];
            const unsigned tbit = (winC >> (j + 2)) & 1u;
            const float t = (float)tbit;

            const float e = __expf(-fabsf(x));
            const float l = __logf(1.f + e);               // log1p(e), e in (0,1]
            const float bce = fmaxf(x, 0.f) - x * t + l;

            const float r = __fdividef(1.f, 1.f + e);
            const float p = (x >= 0.f) ? r : e * r;

            const float ompt = tbit ? (1.f - p) : p;       // 1 - exp(-bce), exact for t in {0,1}
            a_focal += (0.25f * ompt * ompt) * bce;
            a_sp  += p;
            a_st  += t;
            a_spt += tbit ? p : 0.f;

            // diamond radius-2: any (dilate^2) / all (erode^2); OOB bits are 0
            const unsigned c0 = (winC  >> j)       & 0x1Fu;
            const unsigned cu = (winU1 >> (j + 1)) & 0x7u;
            const unsigned cd = (winD1 >> (j + 1)) & 0x7u;
            const unsigned eu = (winU2 >> (j + 2)) & 1u;
            const unsigned ed = (winD2 >> (j + 2)) & 1u;
            const bool any = (c0 | cu | cd | eu | ed) != 0u;
            const bool all = (c0 == 0x1Fu) & (cu == 0x7u) & (cd == 0x7u) & (eu != 0u) & (ed != 0u);
            const float wgt = (any && !all) ? 6.f : 1.f;   // 1 + THETA*boundary
            a_sbw += bce * wgt;
        }
    }

    // ---- block reduction ----
    float v[5] = { a_focal, a_spt, a_sp, a_st, a_sbw };
    #pragma unroll
    for (int q = 0; q < 5; q++) {
        #pragma unroll
        for (int off = 16; off > 0; off >>= 1)
            v[q] += __shfl_down_sync(0xFFFFFFFFu, v[q], off);
    }

    __shared__ float sred[8][5];
    if (lane == 0) {
        #pragma unroll
        for (int q = 0; q < 5; q++) sred[wid][q] = v[q];
    }
    __syncthreads();
    if (threadIdx.x == 0) {
        #pragma unroll
        for (int q = 0; q < 5; q++) {
            float acc = sred[0][q];
            #pragma unroll
            for (int ww = 1; ww < 8; ww++) acc += sred[ww][q];
            g_part[q * MAXBLK + blockIdx.x] = acc;
        }
    }
}

__global__ void __launch_bounds__(256) finalize_kernel(float* out, int nblocks, double invN) {
    double v[5] = { 0.0, 0.0, 0.0, 0.0, 0.0 };
    for (int b = threadIdx.x; b < nblocks; b += 256) {
        #pragma unroll
        for (int q = 0; q < 5; q++) v[q] += (double)g_part[q * MAXBLK + b];
    }
    #pragma unroll
    for (int q = 0; q < 5; q++) {
        #pragma unroll
        for (int off = 16; off > 0; off >>= 1)
            v[q] += __shfl_down_sync(0xFFFFFFFFu, v[q], off);
    }
    __shared__ double sred[8][5];
    const int wid = threadIdx.x >> 5, lane = threadIdx.x & 31;
    if (lane == 0) {
        #pragma unroll
        for (int q = 0; q < 5; q++) sred[wid][q] = v[q];
    }
    __syncthreads();
    if (threadIdx.x == 0) {
        double t[5];
        #pragma unroll
        for (int q = 0; q < 5; q++) {
            double acc = sred[0][q];
            #pragma unroll
            for (int ww = 1; ww < 8; ww++) acc += sred[ww][q];
            t[q] = acc;
        }
        const double focal = t[0] * invN;
        const double dice  = (2.0 * t[1] + 1e-6) / (t[2] + t[3] + 1e-6);
        const double bl    = t[4] * invN;
        out[0] = (float)(0.3 * focal + 0.4 * (1.0 - dice) + 0.3 * bl);
    }
}

extern "C" void kernel_launch(void* const* d_in, const int* in_sizes, int n_in,
                              void* d_out, int out_size) {
    const float* inp = (const float*)d_in[0];
    const float* tgt = (const float*)d_in[1];
    const int N = in_sizes[0];
    const int nimg = N / HWSZ;
    const int nblocks = nimg * (HH / TILE_ROWS);

    combined_loss_kernel<<<nblocks, 256>>>(inp, tgt);
    finalize_kernel<<<1, 256>>>((float*)d_out, nblocks, 1.0 / (double)N);
}

// round 4
// speedup vs baseline: 1.9111x; 1.9111x over previous
#include <cuda_runtime.h>

#define HH 512
#define WW 512
#define HWSZ (HH * WW)
#define RSTRIP 16
#define MAXBLK 2048

// partials layout: g_part[q * MAXBLK + block], q: 0=focal 1=sum(p*t) 2=sum(p) 3=sum(t) 4=sum(bce*w)
__device__ float g_part[5 * MAXBLK];
__device__ unsigned g_cnt;   // zero-initialized; last block resets it each launch

// 8-bit window for row gy, columns x0-2 .. x0+5 (bit k <-> col x0-2+k). OOB bits = 0.
// targets are exactly 0.0f (0x00000000) or 1.0f (0x3F800000): bit 29 distinguishes them.
__device__ __forceinline__ unsigned win_load(const float* __restrict__ tb, int gy, int x0) {
    unsigned b = 0u;
    if ((unsigned)gy < (unsigned)HH) {
        const float* row = tb + gy * WW;
        uint4 c = *reinterpret_cast<const uint4*>(row + x0);
        b = (((c.x >> 29) & 1u) << 2) | (((c.y >> 29) & 1u) << 3) |
            (((c.z >> 29) & 1u) << 4) | (((c.w >> 29) & 1u) << 5);
        if (x0 > 0) {
            uint2 l = *reinterpret_cast<const uint2*>(row + x0 - 2);
            b |= ((l.x >> 29) & 1u) | (((l.y >> 29) & 1u) << 1);
        }
        if (x0 + 4 < WW) {
            uint2 r = *reinterpret_cast<const uint2*>(row + x0 + 4);
            b |= (((r.x >> 29) & 1u) << 6) | (((r.y >> 29) & 1u) << 7);
        }
    }
    return b;
}

__global__ void __launch_bounds__(256) combined_loss_kernel(
    const float* __restrict__ inp,
    const float* __restrict__ tgt,
    float* __restrict__ out,
    double invN)
{
    const int b    = blockIdx.x;
    const int img  = b >> 4;                       // 16 strip-pairs per image
    const int pair = b & 15;
    const int tid  = threadIdx.x;
    const int strip = (pair << 1) | (tid >> 7);    // 0..31
    const int x0    = (tid & 127) << 2;
    const int y0    = strip * RSTRIP;

    const float* tb = tgt + (size_t)img * HWSZ;
    const float* ib = inp + (size_t)img * HWSZ;

    // rolling window registers for rows y-2..y+1 (y = y0 at loop entry)
    unsigned wm2 = win_load(tb, y0 - 2, x0);
    unsigned wm1 = win_load(tb, y0 - 1, x0);
    unsigned w0  = win_load(tb, y0,     x0);
    unsigned wp1 = win_load(tb, y0 + 1, x0);

    float a0 = 0.f, a1 = 0.f, a2 = 0.f, a3 = 0.f, a4 = 0.f;

    #pragma unroll 4
    for (int r = 0; r < RSTRIP; r++) {
        const int gy = y0 + r;
        const unsigned wp2 = win_load(tb, gy + 2, x0);
        const float4 xi = *reinterpret_cast<const float4*>(ib + gy * WW + x0);
        const float xv[4] = { xi.x, xi.y, xi.z, xi.w };

        #pragma unroll
        for (int j = 0; j < 4; j++) {
            const float x = xv[j];
            const unsigned tbit = (w0 >> (j + 2)) & 1u;
            const float t = (float)tbit;

            const float e = __expf(-fabsf(x));
            const float l = __logf(1.f + e);           // log1p(e), e in (0,1]
            const float bce = fmaxf(x, 0.f) - x * t + l;

            const float rr = __fdividef(1.f, 1.f + e);
            const float p = (x >= 0.f) ? rr : e * rr;

            const float ompt = tbit ? (1.f - p) : p;   // 1 - exp(-bce), exact for t in {0,1}
            a0 += (0.25f * ompt * ompt) * bce;
            a2 += p;
            a3 += t;
            a1 += tbit ? p : 0.f;

            // diamond radius-2: any (dilate^2) vs all (erode^2)
            const unsigned c0 = (w0  >> j)       & 0x1Fu;
            const unsigned cu = (wm1 >> (j + 1)) & 0x7u;
            const unsigned cd = (wp1 >> (j + 1)) & 0x7u;
            const unsigned eu = (wm2 >> (j + 2)) & 1u;
            const unsigned ed = (wp2 >> (j + 2)) & 1u;
            const bool any = (c0 | cu | cd | eu | ed) != 0u;
            const bool all = (c0 == 0x1Fu) & (cu == 0x7u) & (cd == 0x7u) & (eu != 0u) & (ed != 0u);
            const float wgt = (any && !all) ? 6.f : 1.f;  // 1 + THETA*boundary
            a4 += bce * wgt;
        }

        wm2 = wm1; wm1 = w0; w0 = wp1; wp1 = wp2;
    }

    // ---- block reduction ----
    float v[5] = { a0, a1, a2, a3, a4 };
    #pragma unroll
    for (int q = 0; q < 5; q++) {
        #pragma unroll
        for (int off = 16; off > 0; off >>= 1)
            v[q] += __shfl_down_sync(0xFFFFFFFFu, v[q], off);
    }

    __shared__ float sred[8][5];
    const int wid  = tid >> 5;
    const int lane = tid & 31;
    if (lane == 0) {
        #pragma unroll
        for (int q = 0; q < 5; q++) sred[wid][q] = v[q];
    }
    __syncthreads();

    __shared__ bool isLast;
    if (tid == 0) {
        #pragma unroll
        for (int q = 0; q < 5; q++) {
            float acc = sred[0][q];
            #pragma unroll
            for (int w = 1; w < 8; w++) acc += sred[w][q];
            g_part[q * MAXBLK + b] = acc;
        }
        __threadfence();
        const unsigned done = atomicAdd(&g_cnt, 1u);
        isLast = (done == gridDim.x - 1);
    }
    __syncthreads();

    // ---- last block folds the partials and writes the scalar ----
    if (isLast) {
        __threadfence();
        const int nb = gridDim.x;
        double d[5] = { 0.0, 0.0, 0.0, 0.0, 0.0 };
        for (int i = tid; i < nb; i += 256) {
            #pragma unroll
            for (int q = 0; q < 5; q++) d[q] += (double)g_part[q * MAXBLK + i];
        }
        #pragma unroll
        for (int q = 0; q < 5; q++) {
            #pragma unroll
            for (int off = 16; off > 0; off >>= 1)
                d[q] += __shfl_down_sync(0xFFFFFFFFu, d[q], off);
        }
        __shared__ double dred[8][5];
        if (lane == 0) {
            #pragma unroll
            for (int q = 0; q < 5; q++) dred[wid][q] = d[q];
        }
        __syncthreads();
        if (tid == 0) {
            double t[5];
            #pragma unroll
            for (int q = 0; q < 5; q++) {
                double acc = dred[0][q];
                #pragma unroll
                for (int w = 1; w < 8; w++) acc += dred[w][q];
                t[q] = acc;
            }
            const double focal = t[0] * invN;
            const double dice  = (2.0 * t[1] + 1e-6) / (t[2] + t[3] + 1e-6);
            const double bl    = t[4] * invN;
            out[0] = (float)(0.3 * focal + 0.4 * (1.0 - dice) + 0.3 * bl);
            g_cnt = 0;   // reset for next graph replay
        }
    }
}

extern "C" void kernel_launch(void* const* d_in, const int* in_sizes, int n_in,
                              void* d_out, int out_size) {
    const float* inp = (const float*)d_in[0];
    const float* tgt = (const float*)d_in[1];
    const int N = in_sizes[0];
    const int nimg = N / HWSZ;
    const int nblocks = nimg * 16;   // 16 strip-pairs (32 strips of 16 rows) per image

    combined_loss_kernel<<<nblocks, 256>>>(inp, tgt, (float*)d_out, 1.0 / (double)N);
}

// round 5
// speedup vs baseline: 2.1978x; 1.1501x over previous
#include <cuda_runtime.h>

#define HH 512
#define WW 512
#define HWSZ (HH * WW)
#define RSTRIP 16
#define MAXBLK 2048

__device__ float g_part[5 * MAXBLK];
__device__ unsigned g_cnt;   // zero-init; last block resets each launch

// 4-bit mask from 4 target floats (exactly 0.0f / 1.0f): bit29 distinguishes.
__device__ __forceinline__ unsigned mask4(uint4 c) {
    return ((c.x >> 29) & 1u) | (((c.y >> 29) & 1u) << 1) |
           (((c.z >> 29) & 1u) << 2) | (((c.w >> 29) & 1u) << 3);
}

// 12-bit window for row gy, cols x0-2 .. x0+9 (bit k <-> col x0-2+k). OOB bits 0.
__device__ __forceinline__ unsigned win_load8(const float* __restrict__ tb, int gy, int x0) {
    unsigned b = 0u;
    if ((unsigned)gy < (unsigned)HH) {
        const float* row = tb + gy * WW;
        uint4 c0 = *reinterpret_cast<const uint4*>(row + x0);
        uint4 c1 = *reinterpret_cast<const uint4*>(row + x0 + 4);
        b = (mask4(c0) << 2) | (mask4(c1) << 6);
        if (x0 > 0) {
            uint2 l = *reinterpret_cast<const uint2*>(row + x0 - 2);
            b |= ((l.x >> 29) & 1u) | (((l.y >> 29) & 1u) << 1);
        }
        if (x0 + 8 < WW) {
            uint2 r = *reinterpret_cast<const uint2*>(row + x0 + 8);
            b |= (((r.x >> 29) & 1u) << 10) | (((r.y >> 29) & 1u) << 11);
        }
    }
    return b;
}

__device__ __forceinline__ unsigned or5(unsigned x)  { unsigned y = x | (x >> 1); unsigned z = y | (y >> 2); return z | (x >> 4); }
__device__ __forceinline__ unsigned or3(unsigned x)  { return x | (x >> 1) | (x >> 2); }
__device__ __forceinline__ unsigned and5(unsigned x) { unsigned y = x & (x >> 1); unsigned z = y & (y >> 2); return z & (x >> 4); }
__device__ __forceinline__ unsigned and3(unsigned x) { return x & (x >> 1) & (x >> 2); }

__global__ void __launch_bounds__(256) combined_loss_kernel(
    const float* __restrict__ inp,
    const float* __restrict__ tgt,
    float* __restrict__ out,
    double invN)
{
    const int b   = blockIdx.x;
    const int img = b >> 3;                    // 8 blocks per image (64 rows each)
    const int blk = b & 7;
    const int tid = threadIdx.x;
    const int strip = (blk << 2) | (tid >> 6); // 0..31, 16 rows each
    const int x0    = (tid & 63) << 3;         // 8-px column group
    const int y0    = strip * RSTRIP;

    const float* tb = tgt + (size_t)img * HWSZ;
    const float* ib = inp + (size_t)img * HWSZ;

    unsigned wm2 = win_load8(tb, y0 - 2, x0);
    unsigned wm1 = win_load8(tb, y0 - 1, x0);
    unsigned w0  = win_load8(tb, y0,     x0);
    unsigned wp1 = win_load8(tb, y0 + 1, x0);

    float a0 = 0.f, a1 = 0.f, a2 = 0.f, a3 = 0.f, a4 = 0.f;

    #pragma unroll 2
    for (int r = 0; r < RSTRIP; r++) {
        const int gy = y0 + r;
        const unsigned wp2 = win_load8(tb, gy + 2, x0);
        const float4 xa = *reinterpret_cast<const float4*>(ib + gy * WW + x0);
        const float4 xb = *reinterpret_cast<const float4*>(ib + gy * WW + x0 + 4);
        const float xv[8] = { xa.x, xa.y, xa.z, xa.w, xb.x, xb.y, xb.z, xb.w };

        // bit-parallel morphology: result bit j valid for pixels j=0..7
        const unsigned anyb = or5(w0) | (or3(wm1) >> 1) | (or3(wp1) >> 1) | (wm2 >> 2) | (wp2 >> 2);
        const unsigned allb = and5(w0) & (and3(wm1) >> 1) & (and3(wp1) >> 1) & (wm2 >> 2) & (wp2 >> 2);
        const unsigned bnd  = anyb & ~allb;    // boundary bits
        const unsigned tbits = w0 >> 2;        // center bits

        #pragma unroll
        for (int j = 0; j < 8; j++) {
            const float x = xv[j];
            const float t  = (float)((tbits >> j) & 1u);
            const float bf = (float)((bnd   >> j) & 1u);

            const float e = __expf(-fabsf(x));
            const float onePe = 1.f + e;
            const float l = __logf(onePe);                    // log1p(e), e in (0,1]
            const float bce = fmaf(-x, t, fmaxf(x, 0.f) + l);

            const float rr = __fdividef(1.f, onePe);
            const float p  = (x >= 0.f) ? rr : e * rr;

            // 1 - exp(-bce) = t + p - 2tp  (exact for t in {0,1})
            const float ompt = fmaf(t, fmaf(-2.f, p, 1.f), p);
            a0 = fmaf(ompt * ompt, 0.25f * bce, a0);
            a2 += p;
            a3 += t;
            a1 = fmaf(t, p, a1);
            a4 = fmaf(bce, fmaf(5.f, bf, 1.f), a4);          // w = 1 + 5*boundary
        }

        wm2 = wm1; wm1 = w0; w0 = wp1; wp1 = wp2;
    }

    // ---- block reduction ----
    float v[5] = { a0, a1, a2, a3, a4 };
    #pragma unroll
    for (int q = 0; q < 5; q++) {
        #pragma unroll
        for (int off = 16; off > 0; off >>= 1)
            v[q] += __shfl_down_sync(0xFFFFFFFFu, v[q], off);
    }

    __shared__ float sred[8][5];
    const int wid  = tid >> 5;
    const int lane = tid & 31;
    if (lane == 0) {
        #pragma unroll
        for (int q = 0; q < 5; q++) sred[wid][q] = v[q];
    }
    __syncthreads();

    __shared__ bool isLast;
    if (tid == 0) {
        #pragma unroll
        for (int q = 0; q < 5; q++) {
            float acc = sred[0][q];
            #pragma unroll
            for (int w = 1; w < 8; w++) acc += sred[w][q];
            g_part[q * MAXBLK + b] = acc;
        }
        __threadfence();
        isLast = (atomicAdd(&g_cnt, 1u) == gridDim.x - 1);
    }
    __syncthreads();

    if (isLast) {
        __threadfence();
        const int nb = gridDim.x;
        double d[5] = { 0.0, 0.0, 0.0, 0.0, 0.0 };
        for (int i = tid; i < nb; i += 256) {
            #pragma unroll
            for (int q = 0; q < 5; q++) d[q] += (double)g_part[q * MAXBLK + i];
        }
        #pragma unroll
        for (int q = 0; q < 5; q++) {
            #pragma unroll
            for (int off = 16; off > 0; off >>= 1)
                d[q] += __shfl_down_sync(0xFFFFFFFFu, d[q], off);
        }
        __shared__ double dred[8][5];
        if (lane == 0) {
            #pragma unroll
            for (int q = 0; q < 5; q++) dred[wid][q] = d[q];
        }
        __syncthreads();
        if (tid == 0) {
            double t[5];
            #pragma unroll
            for (int q = 0; q < 5; q++) {
                double acc = dred[0][q];
                #pragma unroll
                for (int w = 1; w < 8; w++) acc += dred[w][q];
                t[q] = acc;
            }
            const double focal = t[0] * invN;
            const double dice  = (2.0 * t[1] + 1e-6) / (t[2] + t[3] + 1e-6);
            const double bl    = t[4] * invN;
            out[0] = (float)(0.3 * focal + 0.4 * (1.0 - dice) + 0.3 * bl);
            g_cnt = 0;
        }
    }
}

extern "C" void kernel_launch(void* const* d_in, const int* in_sizes, int n_in,
                              void* d_out, int out_size) {
    const float* inp = (const float*)d_in[0];
    const float* tgt = (const float*)d_in[1];
    const int N = in_sizes[0];
    const int nimg = N / HWSZ;
    const int nblocks = nimg * 8;   // 8 blocks (64 rows) per image

    combined_loss_kernel<<<nblocks, 256>>>(inp, tgt, (float*)d_out, 1.0 / (double)N);
}

// round 6
// speedup vs baseline: 2.4032x; 1.0935x over previous
#include <cuda_runtime.h>

#define HH 512
#define WW 512
#define HWSZ (HH * WW)
#define RSTRIP 8
#define MAXBLK 2048

__device__ float g_part[5 * MAXBLK];
__device__ unsigned g_cnt;   // zero-init; last block resets each launch

// 4-bit mask from 4 target floats (exactly 0.0f / 1.0f): bit29 distinguishes.
__device__ __forceinline__ unsigned mask4(uint4 c) {
    return ((c.x >> 29) & 1u) | (((c.y >> 29) & 1u) << 1) |
           (((c.z >> 29) & 1u) << 2) | (((c.w >> 29) & 1u) << 3);
}

// 12-bit window for row gy, cols x0-2 .. x0+9 (bit k <-> col x0-2+k). OOB bits 0.
__device__ __forceinline__ unsigned win_load8(const float* __restrict__ tb, int gy, int x0) {
    unsigned b = 0u;
    if ((unsigned)gy < (unsigned)HH) {
        const float* row = tb + gy * WW;
        uint4 c0 = *reinterpret_cast<const uint4*>(row + x0);
        uint4 c1 = *reinterpret_cast<const uint4*>(row + x0 + 4);
        b = (mask4(c0) << 2) | (mask4(c1) << 6);
        if (x0 > 0) {
            uint2 l = *reinterpret_cast<const uint2*>(row + x0 - 2);
            b |= ((l.x >> 29) & 1u) | (((l.y >> 29) & 1u) << 1);
        }
        if (x0 + 8 < WW) {
            uint2 r = *reinterpret_cast<const uint2*>(row + x0 + 8);
            b |= (((r.x >> 29) & 1u) << 10) | (((r.y >> 29) & 1u) << 11);
        }
    }
    return b;
}

__device__ __forceinline__ unsigned or5(unsigned x)  { unsigned y = x | (x >> 1); unsigned z = y | (y >> 2); return z | (x >> 4); }
__device__ __forceinline__ unsigned or3(unsigned x)  { return x | (x >> 1) | (x >> 2); }
__device__ __forceinline__ unsigned and5(unsigned x) { unsigned y = x & (x >> 1); unsigned z = y & (y >> 2); return z & (x >> 4); }
__device__ __forceinline__ unsigned and3(unsigned x) { return x & (x >> 1) & (x >> 2); }

__global__ void __launch_bounds__(256) combined_loss_kernel(
    const float* __restrict__ inp,
    const float* __restrict__ tgt,
    float* __restrict__ out,
    double invN)
{
    const int b   = blockIdx.x;
    const int img = b >> 4;                     // 16 blocks per image (32 rows each)
    const int blk = b & 15;
    const int tid = threadIdx.x;
    const int strip = (blk << 2) | (tid >> 6);  // 0..63 strips of 8 rows
    const int x0    = (tid & 63) << 3;          // 8-px column group
    const int y0    = strip * RSTRIP;

    const float* tb = tgt + (size_t)img * HWSZ;
    const float* ib = inp + (size_t)img * HWSZ;

    unsigned wm2 = win_load8(tb, y0 - 2, x0);
    unsigned wm1 = win_load8(tb, y0 - 1, x0);
    unsigned w0  = win_load8(tb, y0,     x0);
    unsigned wp1 = win_load8(tb, y0 + 1, x0);

    float a0 = 0.f, a1 = 0.f, a2 = 0.f, a4n = 0.f, a4b = 0.f;
    int   a3i = 0;

    #pragma unroll
    for (int r = 0; r < RSTRIP; r++) {
        const int gy = y0 + r;
        const unsigned wp2 = win_load8(tb, gy + 2, x0);
        const float4 xa = *reinterpret_cast<const float4*>(ib + gy * WW + x0);
        const float4 xb = *reinterpret_cast<const float4*>(ib + gy * WW + x0 + 4);
        const float xv[8] = { xa.x, xa.y, xa.z, xa.w, xb.x, xb.y, xb.z, xb.w };

        // bit-parallel morphology: bit j valid for pixels j=0..7
        const unsigned anyb = or5(w0) | (or3(wm1) >> 1) | (or3(wp1) >> 1) | (wm2 >> 2) | (wp2 >> 2);
        const unsigned allb = and5(w0) & (and3(wm1) >> 1) & (and3(wp1) >> 1) & (wm2 >> 2) & (wp2 >> 2);
        const unsigned bnd   = anyb & ~allb;
        const unsigned tbits = (w0 >> 2) & 0xFFu;

        a3i += __popc(tbits);                   // sum(t) for this row

        #pragma unroll
        for (int j = 0; j < 8; j++) {
            const float x = xv[j];
            const bool tb1 = (tbits >> j) & 1u;
            const bool bb1 = (bnd   >> j) & 1u;

            const float e = __expf(-fabsf(x));
            const float onePe = 1.f + e;
            const float l = __logf(onePe);                 // log1p(e), e in (0,1]

            const float rr = __fdividef(1.f, onePe);
            const float p  = (x >= 0.f) ? rr : e * rr;

            const float base = fmaxf(x, 0.f) + l;
            const float bce  = tb1 ? base - x : base;

            const float ompt = tb1 ? 1.f - p : p;          // 1 - exp(-bce)
            a0 = fmaf(ompt * ompt, bce, a0);               // 0.25 applied at partial write
            a2 += p;
            a1 += tb1 ? p : 0.f;
            a4n += bce;
            a4b += bb1 ? bce : 0.f;
        }

        wm2 = wm1; wm1 = w0; w0 = wp1; wp1 = wp2;
    }

    // ---- block reduction ----
    float v[5] = { 0.25f * a0, a1, a2, (float)a3i, fmaf(5.f, a4b, a4n) };
    #pragma unroll
    for (int q = 0; q < 5; q++) {
        #pragma unroll
        for (int off = 16; off > 0; off >>= 1)
            v[q] += __shfl_down_sync(0xFFFFFFFFu, v[q], off);
    }

    __shared__ float sred[8][5];
    const int wid  = tid >> 5;
    const int lane = tid & 31;
    if (lane == 0) {
        #pragma unroll
        for (int q = 0; q < 5; q++) sred[wid][q] = v[q];
    }
    __syncthreads();

    __shared__ bool isLast;
    if (tid == 0) {
        #pragma unroll
        for (int q = 0; q < 5; q++) {
            float acc = sred[0][q];
            #pragma unroll
            for (int w = 1; w < 8; w++) acc += sred[w][q];
            g_part[q * MAXBLK + b] = acc;
        }
        __threadfence();
        isLast = (atomicAdd(&g_cnt, 1u) == gridDim.x - 1);
    }
    __syncthreads();

    if (isLast) {
        __threadfence();
        const int nb = gridDim.x;
        double d[5] = { 0.0, 0.0, 0.0, 0.0, 0.0 };
        for (int i = tid; i < nb; i += 256) {
            #pragma unroll
            for (int q = 0; q < 5; q++) d[q] += (double)g_part[q * MAXBLK + i];
        }
        #pragma unroll
        for (int q = 0; q < 5; q++) {
            #pragma unroll
            for (int off = 16; off > 0; off >>= 1)
                d[q] += __shfl_down_sync(0xFFFFFFFFu, d[q], off);
        }
        __shared__ double dred[8][5];
        if (lane == 0) {
            #pragma unroll
            for (int q = 0; q < 5; q++) dred[wid][q] = d[q];
        }
        __syncthreads();
        if (tid == 0) {
            double t[5];
            #pragma unroll
            for (int q = 0; q < 5; q++) {
                double acc = dred[0][q];
                #pragma unroll
                for (int w = 1; w < 8; w++) acc += dred[w][q];
                t[q] = acc;
            }
            const double focal = t[0] * invN;
            const double dice  = (2.0 * t[1] + 1e-6) / (t[2] + t[3] + 1e-6);
            const double bl    = t[4] * invN;
            out[0] = (float)(0.3 * focal + 0.4 * (1.0 - dice) + 0.3 * bl);
            g_cnt = 0;
        }
    }
}

extern "C" void kernel_launch(void* const* d_in, const int* in_sizes, int n_in,
                              void* d_out, int out_size) {
    const float* inp = (const float*)d_in[0];
    const float* tgt = (const float*)d_in[1];
    const int N = in_sizes[0];
    const int nimg = N / HWSZ;
    const int nblocks = nimg * 16;   // 16 blocks (32 rows) per image

    combined_loss_kernel<<<nblocks, 256>>>(inp, tgt, (float*)d_out, 1.0 / (double)N);
}

// round 7
// speedup vs baseline: 2.4264x; 1.0097x over previous
#include <cuda_runtime.h>

#define HH 512
#define WW 512
#define HWSZ (HH * WW)
#define RSTRIP 8
#define MAXBLK 2048

__device__ float g_part[6 * MAXBLK];
__device__ unsigned g_cnt;   // zero-init; last block resets each launch

// pack top-bit-29 of 8 target floats (0.0f/1.0f) into bits 0..7.
// byte3 of 1.0f is 0x3F, of 0.0f is 0x00.
__device__ __forceinline__ unsigned pack8(uint4 c0, uint4 c1) {
    unsigned a = __byte_perm(__byte_perm(c0.x, c0.y, 0x0073),
                             __byte_perm(c0.z, c0.w, 0x0073), 0x5410);
    unsigned b = __byte_perm(__byte_perm(c1.x, c1.y, 0x0073),
                             __byte_perm(c1.z, c1.w, 0x0073), 0x5410);
    unsigned ba = ((a & 0x01010101u) * 0x01020408u) >> 24;  // px0..3 -> bits0..3
    unsigned bb = ((b & 0x01010101u) * 0x01020408u) >> 24;  // px4..7 -> bits0..3
    return ba | (bb << 4);
}

// 12-bit window for row gy, cols x0-2 .. x0+9 (bit k <-> col x0-2+k). OOB bits 0.
__device__ __forceinline__ unsigned win_load8(const float* __restrict__ tb, int gy, int x0) {
    unsigned w = 0u;
    if ((unsigned)gy < (unsigned)HH) {
        const float* row = tb + gy * WW;
        uint4 c0 = *reinterpret_cast<const uint4*>(row + x0);
        uint4 c1 = *reinterpret_cast<const uint4*>(row + x0 + 4);
        w = pack8(c0, c1) << 2;
        if (x0 > 0) {
            uint2 l = *reinterpret_cast<const uint2*>(row + x0 - 2);
            w |= ((l.x >> 29) & 1u) | (((l.y >> 29) & 1u) << 1);
        }
        if (x0 + 8 < WW) {
            uint2 r = *reinterpret_cast<const uint2*>(row + x0 + 8);
            w |= (((r.x >> 29) & 1u) << 10) | (((r.y >> 29) & 1u) << 11);
        }
    }
    return w;
}

__device__ __forceinline__ unsigned or5(unsigned x)  { unsigned y = x | (x >> 1); unsigned z = y | (y >> 2); return z | (x >> 4); }
__device__ __forceinline__ unsigned or3(unsigned x)  { return x | (x >> 1) | (x >> 2); }
__device__ __forceinline__ unsigned and5(unsigned x) { unsigned y = x & (x >> 1); unsigned z = y & (y >> 2); return z & (x >> 4); }
__device__ __forceinline__ unsigned and3(unsigned x) { return x & (x >> 1) & (x >> 2); }

__device__ __forceinline__ float tanh_approx(float x) {
    float r;
    asm("tanh.approx.f32 %0, %1;" : "=f"(r) : "f"(x));
    return r;
}

__global__ void __launch_bounds__(256) combined_loss_kernel(
    const float* __restrict__ inp,
    const float* __restrict__ tgt,
    float* __restrict__ out,
    float invN)
{
    const int b   = blockIdx.x;
    const int img = b >> 4;                     // 16 blocks per image (32 rows each)
    const int blk = b & 15;
    const int tid = threadIdx.x;
    const int strip = (blk << 2) | (tid >> 6);  // 0..63 strips of 8 rows
    const int x0    = (tid & 63) << 3;          // 8-px column group
    const int y0    = strip * RSTRIP;

    const float* tb = tgt + (size_t)img * HWSZ;
    const float* ib = inp + (size_t)img * HWSZ;

    unsigned wm2 = win_load8(tb, y0 - 2, x0);
    unsigned wm1 = win_load8(tb, y0 - 1, x0);
    unsigned w0  = win_load8(tb, y0,     x0);
    unsigned wp1 = win_load8(tb, y0 + 1, x0);

    float aF = 0.f;   // sum ompt^2 * bce
    float aW = 0.f;   // sum (t-0.5)*pt
    float aU = 0.f;   // sum pt
    float aB = 0.f;   // sum bce
    float aY = 0.f;   // sum (bnd-0.5)*bce
    int   aT = 0;     // sum t (popc)

    #pragma unroll
    for (int r = 0; r < RSTRIP; r++) {
        const int gy = y0 + r;
        const unsigned wp2 = win_load8(tb, gy + 2, x0);
        const float4 xa = *reinterpret_cast<const float4*>(ib + gy * WW + x0);
        const float4 xb = *reinterpret_cast<const float4*>(ib + gy * WW + x0 + 4);
        const float xv[8] = { xa.x, xa.y, xa.z, xa.w, xb.x, xb.y, xb.z, xb.w };

        // bit-parallel morphology: bit j valid for pixels j=0..7
        const unsigned anyb = or5(w0) | (or3(wm1) >> 1) | (or3(wp1) >> 1) | (wm2 >> 2) | (wp2 >> 2);
        const unsigned allb = and5(w0) & (and3(wm1) >> 1) & (and3(wp1) >> 1) & (wm2 >> 2) & (wp2 >> 2);
        const unsigned bnd   = anyb & ~allb;
        const unsigned tbits = (w0 >> 2) & 0xFFu;

        aT += __popc(tbits);

        const unsigned nt = ~tbits;   // for sign-bit construction
        const unsigned nb = ~bnd;

        #pragma unroll
        for (int j = 0; j < 8; j++) {
            const float x = xv[j];
            // sgn_t = +0.5 if t==1 else -0.5 (sign bit from ~t), likewise sgn_b
            const float sgt = __uint_as_float(((nt << (31 - j)) & 0x80000000u) | 0x3F000000u);
            const float sgb = __uint_as_float(((nb << (31 - j)) & 0x80000000u) | 0x3F000000u);

            const float th = tanh_approx(0.5f * x);
            const float pt = fmaf(sgt, th, 0.5f);       // prob of true class
            const float bce = -__logf(pt);
            const float ompt = fmaf(sgt, -th, 0.5f);    // 1 - pt

            aU += pt;
            aW = fmaf(sgt, pt, aW);
            aF = fmaf(ompt * ompt, bce, aF);
            aB += bce;
            aY = fmaf(sgb, bce, aY);
        }

        wm2 = wm1; wm1 = w0; w0 = wp1; wp1 = wp2;
    }

    // ---- block reduction (6 quantities) ----
    float v[6] = { aF, aW, aU, (float)aT, aB, aY };
    #pragma unroll
    for (int q = 0; q < 6; q++) {
        #pragma unroll
        for (int off = 16; off > 0; off >>= 1)
            v[q] += __shfl_down_sync(0xFFFFFFFFu, v[q], off);
    }

    __shared__ float sred[8][6];
    const int wid  = tid >> 5;
    const int lane = tid & 31;
    if (lane == 0) {
        #pragma unroll
        for (int q = 0; q < 6; q++) sred[wid][q] = v[q];
    }
    __syncthreads();

    __shared__ bool isLast;
    if (tid == 0) {
        #pragma unroll
        for (int q = 0; q < 6; q++) {
            float acc = sred[0][q];
            #pragma unroll
            for (int w = 1; w < 8; w++) acc += sred[w][q];
            g_part[q * MAXBLK + b] = acc;
        }
        __threadfence();
        isLast = (atomicAdd(&g_cnt, 1u) == gridDim.x - 1);
    }
    __syncthreads();

    if (isLast) {
        __threadfence();
        const int nb2 = gridDim.x;
        double d[6] = { 0, 0, 0, 0, 0, 0 };
        for (int i = tid; i < nb2; i += 256) {
            #pragma unroll
            for (int q = 0; q < 6; q++) d[q] += (double)g_part[q * MAXBLK + i];
        }
        #pragma unroll
        for (int q = 0; q < 6; q++) {
            #pragma unroll
            for (int off = 16; off > 0; off >>= 1)
                d[q] += __shfl_down_sync(0xFFFFFFFFu, d[q], off);
        }
        __shared__ double dred[8][6];
        if (lane == 0) {
            #pragma unroll
            for (int q = 0; q < 6; q++) dred[wid][q] = d[q];
        }
        __syncthreads();
        if (tid == 0) {
            double t[6];
            #pragma unroll
            for (int q = 0; q < 6; q++) {
                double acc = dred[0][q];
                #pragma unroll
                for (int w = 1; w < 8; w++) acc += dred[w][q];
                t[q] = acc;
            }
            const double N  = 1.0 / (double)invN;
            const double T  = t[3];
            const double V  = t[1] + 0.5 * t[2];      // sum(p*t)
            const double sumP = 2.0 * t[1] + (N - T); // sum(p)
            const double focal = 0.25 * t[0] / N;
            const double dice  = (2.0 * V + 1e-6) / (sumP + T + 1e-6);
            const double bl    = (3.5 * t[4] + 5.0 * t[5]) / N;
            out[0] = (float)(0.3 * focal + 0.4 * (1.0 - dice) + 0.3 * bl);
            g_cnt = 0;
        }
    }
}

extern "C" void kernel_launch(void* const* d_in, const int* in_sizes, int n_in,
                              void* d_out, int out_size) {
    const float* inp = (const float*)d_in[0];
    const float* tgt = (const float*)d_in[1];
    const int N = in_sizes[0];
    const int nimg = N / HWSZ;
    const int nblocks = nimg * 16;   // 16 blocks (32 rows) per image

    combined_loss_kernel<<<nblocks, 256>>>(inp, tgt, (float*)d_out, 1.0f / (float)N);
}